// round 1
// baseline (speedup 1.0000x reference)
#include <cuda_runtime.h>
#include <cstdint>
#include <cstddef>

#define B 32
#define T 512
#define D 500
#define H 10
#define HD 50
#define D3 1500
#define BT (B*T)
#define BTD (BT*D)
#define KW 7

// ---------------- scratch (static device arrays; no runtime allocation) ----
__device__ float g_b0[BTD];
__device__ float g_b1[BTD];
__device__ float g_b2[BTD];
__device__ float g_bt[BTD];
__device__ float g_qkv[(size_t)BT * D3];

// ---------------- positional embedding + add ------------------------------
__global__ void posemb_kernel(const int* __restrict__ ori,
                              const float* __restrict__ x,
                              float* __restrict__ out) {
    int idx = blockIdx.x * blockDim.x + threadIdx.x;
    if (idx >= BTD) return;
    int d  = idx % D;
    int bt = idx / D;
    int t  = bt % T;
    float pe = 0.f;
    if (ori[bt] != 0) {
        float pos = (float)(t + 1);
        int   i   = (d < 250) ? d : (d - 250);
        // inv = exp(i * (-ln(10000)/249))
        float ang = pos * expf((float)i * -0.036989318763f);
        pe = (d < 250) ? sinf(ang) : cosf(ang);
    }
    out[idx] = pe + x[idx];
}

// ---------------- depthwise conv1d (k=7, pad=3) ----------------------------
__global__ void dwconv_kernel(const float* __restrict__ x,
                              const float* __restrict__ w,
                              const float* __restrict__ bias,
                              float* __restrict__ y) {
    int idx = blockIdx.x * blockDim.x + threadIdx.x;
    if (idx >= BTD) return;
    int d  = idx % D;
    int bt = idx / D;
    int t  = bt % T;
    int b  = bt / T;
    const float* wd = w + d * KW;
    float acc = bias[d];
    const float* xb = x + (size_t)(b * T) * D + d;
#pragma unroll
    for (int j = 0; j < KW; j++) {
        int tt = t + j - 3;
        if (tt >= 0 && tt < T) acc = fmaf(wd[j], xb[(size_t)tt * D], acc);
    }
    y[idx] = acc;
}

// ---------------- SGEMM: C[M,N] = A[M,K]*W[N,K]^T + bias (+ res) -----------
#define BM 128
#define BN 128
#define BKK 8
#define TM 8
#define TN 8

__global__ __launch_bounds__(256)
void gemm_kernel(const float* __restrict__ A, const float* __restrict__ W,
                 const float* __restrict__ bias, const float* __restrict__ res,
                 float* __restrict__ C, int N, int Kd) {
    __shared__ float As[BKK][BM];
    __shared__ float Bs[BKK][BN];
    int tid = threadIdx.x;
    int m0 = blockIdx.y * BM;
    int n0 = blockIdx.x * BN;
    int ty = tid >> 4, tx = tid & 15;

    int lrow = tid >> 1;          // 0..127
    int lk   = (tid & 1) * 4;     // 0 or 4

    const float* Arow = A + (size_t)(m0 + lrow) * Kd;
    bool wvalid = (n0 + lrow) < N;
    const float* Wrow = W + (size_t)(wvalid ? (n0 + lrow) : 0) * Kd;

    float acc[TM][TN];
#pragma unroll
    for (int i = 0; i < TM; i++)
#pragma unroll
        for (int j = 0; j < TN; j++) acc[i][j] = 0.f;

    int ktiles = (Kd + BKK - 1) / BKK;
    for (int kt = 0; kt < ktiles; kt++) {
        int k0 = kt * BKK;
#pragma unroll
        for (int r = 0; r < 4; r++) {
            int kk = k0 + lk + r;
            bool kin = (kk < Kd);
            As[lk + r][lrow] = kin ? Arow[kk] : 0.f;
            Bs[lk + r][lrow] = (kin && wvalid) ? Wrow[kk] : 0.f;
        }
        __syncthreads();
#pragma unroll
        for (int k = 0; k < BKK; k++) {
            float a[TM], bb[TN];
            *(float4*)&a[0]  = *(const float4*)&As[k][ty * TM];
            *(float4*)&a[4]  = *(const float4*)&As[k][ty * TM + 4];
            *(float4*)&bb[0] = *(const float4*)&Bs[k][tx * TN];
            *(float4*)&bb[4] = *(const float4*)&Bs[k][tx * TN + 4];
#pragma unroll
            for (int i = 0; i < TM; i++)
#pragma unroll
                for (int j = 0; j < TN; j++)
                    acc[i][j] = fmaf(a[i], bb[j], acc[i][j]);
        }
        __syncthreads();
    }

#pragma unroll
    for (int i = 0; i < TM; i++) {
        int row = m0 + ty * TM + i;
        float* crow = C + (size_t)row * N;
        const float* rrow = res ? (res + (size_t)row * N) : nullptr;
#pragma unroll
        for (int j = 0; j < TN; j++) {
            int col = n0 + tx * TN + j;
            if (col < N) {
                float v = acc[i][j] + bias[col];
                if (res) v += rrow[col];
                crow[col] = v;
            }
        }
    }
}

// ---------------- fused flash attention ------------------------------------
// grid: (T/QT, B*H), block 256. Q/K tiles 64x50 (HD), padded PV to 64 cols.
#define QT 64
#define KTL 64
#define SP 64

__global__ __launch_bounds__(256)
void attn_kernel(const float* __restrict__ qkv,
                 const unsigned char* __restrict__ mask,
                 float* __restrict__ out) {
    __shared__ float Qt[HD][SP];     // Q transposed [d][i], pre-scaled
    __shared__ float KtS[KTL][SP];   // phase 1: Kt[d][j] (d<50); phase 2: S^T [j][i]
    __shared__ float Vs[KTL][SP];    // V [j][c], cols 50..63 zero
    __shared__ float corr_s[QT];
    __shared__ float l_s[QT];
    __shared__ unsigned char msk[KTL];

    int tid = threadIdx.x;
    int bh  = blockIdx.y;
    int b   = bh / H, h = bh % H;
    int q0  = blockIdx.x * QT;
    int ty  = tid >> 4, tx = tid & 15;
    const float scale = 0.14142135623730951f;  // 50^-0.5

    const float* qbase = qkv + (size_t)(b * T + q0) * D3 + h * HD;
    for (int idx = tid; idx < QT * HD; idx += 256) {
        int i = idx / HD, d = idx % HD;
        Qt[d][i] = qbase[(size_t)i * D3 + d] * scale;
    }
    for (int idx = tid; idx < KTL * (SP - HD); idx += 256) {
        int j = idx / (SP - HD), c = HD + idx % (SP - HD);
        Vs[j][c] = 0.f;
    }

    float o[4][4];
#pragma unroll
    for (int i = 0; i < 4; i++)
#pragma unroll
        for (int j = 0; j < 4; j++) o[i][j] = 0.f;
    float m_i = -1e30f, l_i = 0.f;

    for (int kt = 0; kt < T / KTL; kt++) {
        int k0 = kt * KTL;
        __syncthreads();  // previous tile fully consumed
        const float* kbase = qkv + (size_t)(b * T + k0) * D3 + D + h * HD;
        const float* vbase = kbase + D;
        for (int idx = tid; idx < KTL * HD; idx += 256) {
            int j = idx / HD, d = idx % HD;
            KtS[d][j] = kbase[(size_t)j * D3 + d];
            Vs[j][d]  = vbase[(size_t)j * D3 + d];
        }
        if (tid < KTL) msk[tid] = mask[b * T + k0 + tid];
        __syncthreads();

        // S = Q * K^T (thread tile 4x4), reads all within-smem-row -> conflict free
        float s[4][4];
#pragma unroll
        for (int i = 0; i < 4; i++)
#pragma unroll
            for (int j = 0; j < 4; j++) s[i][j] = 0.f;
#pragma unroll
        for (int d = 0; d < HD; d++) {
            float4 aq = *(const float4*)&Qt[d][ty * 4];
            float4 bk = *(const float4*)&KtS[d][tx * 4];
            float qa[4] = {aq.x, aq.y, aq.z, aq.w};
            float kb[4] = {bk.x, bk.y, bk.z, bk.w};
#pragma unroll
            for (int i = 0; i < 4; i++)
#pragma unroll
                for (int j = 0; j < 4; j++)
                    s[i][j] = fmaf(qa[i], kb[j], s[i][j]);
        }
        __syncthreads();  // everyone done reading Kt; reuse as S^T

#pragma unroll
        for (int jj = 0; jj < 4; jj++) {
            int j = tx * 4 + jj;
            bool mk = (msk[j] != 0);
            float4 v;
            v.x = mk ? -1e30f : s[0][jj];
            v.y = mk ? -1e30f : s[1][jj];
            v.z = mk ? -1e30f : s[2][jj];
            v.w = mk ? -1e30f : s[3][jj];
            *(float4*)&KtS[j][ty * 4] = v;   // S^T[j][i]
        }
        __syncthreads();

        // online softmax, one thread per q-row
        if (tid < QT) {
            int i = tid;
            float tmax = -1e30f;
#pragma unroll 8
            for (int j = 0; j < KTL; j++) tmax = fmaxf(tmax, KtS[j][i]);
            float mnew = fmaxf(m_i, tmax);
            float c = expf(m_i - mnew);
            float ls = 0.f;
#pragma unroll 8
            for (int j = 0; j < KTL; j++) {
                float p = expf(KtS[j][i] - mnew);
                KtS[j][i] = p;
                ls += p;
            }
            l_i = l_i * c + ls;
            m_i = mnew;
            corr_s[i] = c;
            l_s[i] = l_i;
        }
        __syncthreads();

        // O = O*corr + P*V (thread tile 4x4)
#pragma unroll
        for (int i = 0; i < 4; i++) {
            float c = corr_s[ty * 4 + i];
#pragma unroll
            for (int j = 0; j < 4; j++) o[i][j] *= c;
        }
#pragma unroll 8
        for (int j = 0; j < KTL; j++) {
            float4 p4 = *(const float4*)&KtS[j][ty * 4];
            float4 v4 = *(const float4*)&Vs[j][tx * 4];
            float pa[4] = {p4.x, p4.y, p4.z, p4.w};
            float vb[4] = {v4.x, v4.y, v4.z, v4.w};
#pragma unroll
            for (int i = 0; i < 4; i++)
#pragma unroll
                for (int jj = 0; jj < 4; jj++)
                    o[i][jj] = fmaf(pa[i], vb[jj], o[i][jj]);
        }
    }

    float* obase = out + (size_t)(b * T + q0) * D + h * HD;
#pragma unroll
    for (int i = 0; i < 4; i++) {
        int row = ty * 4 + i;
        float inv = 1.f / l_s[row];
#pragma unroll
        for (int j = 0; j < 4; j++) {
            int c = tx * 4 + j;
            if (c < HD) obase[(size_t)row * D + c] = o[i][j] * inv;
        }
    }
}

// ---------------- launch ----------------------------------------------------
extern "C" void kernel_launch(void* const* d_in, const int* in_sizes, int n_in,
                              void* d_out, int out_size) {
    const int* ori            = (const int*)d_in[0];
    const float* x            = (const float*)d_in[1];
    const unsigned char* xm   = (const unsigned char*)d_in[2];
    const float *dwp[4], *dbp[4], *pwp[4], *pbp[4];
    for (int i = 0; i < 4; i++) {
        dwp[i] = (const float*)d_in[3 + 4 * i];
        dbp[i] = (const float*)d_in[4 + 4 * i];
        pwp[i] = (const float*)d_in[5 + 4 * i];
        pbp[i] = (const float*)d_in[6 + 4 * i];
    }
    const float* in_w  = (const float*)d_in[19];
    const float* in_b  = (const float*)d_in[20];
    const float* out_w = (const float*)d_in[21];
    const float* out_b = (const float*)d_in[22];
    const float* ffc_w = (const float*)d_in[23];
    const float* ffc_b = (const float*)d_in[24];
    float* outp = (float*)d_out;

    float *b0, *b1, *b2, *bt, *qkvp;
    cudaGetSymbolAddress((void**)&b0,   g_b0);
    cudaGetSymbolAddress((void**)&b1,   g_b1);
    cudaGetSymbolAddress((void**)&b2,   g_b2);
    cudaGetSymbolAddress((void**)&bt,   g_bt);
    cudaGetSymbolAddress((void**)&qkvp, g_qkv);

    int eblocks = (BTD + 255) / 256;
    dim3 gg5((D + BN - 1) / BN, BT / BM);    // (4, 128)
    dim3 ggq((D3 + BN - 1) / BN, BT / BM);   // (12, 128)
    dim3 gga(T / QT, B * H);                 // (8, 320)

    // x0 = pos_emb + x
    posemb_kernel<<<eblocks, 256>>>(ori, x, b0);
    // 4 separable conv blocks with residual
    dwconv_kernel<<<eblocks, 256>>>(b0, dwp[0], dbp[0], bt);
    gemm_kernel<<<gg5, 256>>>(bt, pwp[0], pbp[0], b0, b1, D, D);
    dwconv_kernel<<<eblocks, 256>>>(b1, dwp[1], dbp[1], bt);
    gemm_kernel<<<gg5, 256>>>(bt, pwp[1], pbp[1], b1, b2, D, D);
    dwconv_kernel<<<eblocks, 256>>>(b2, dwp[2], dbp[2], bt);
    gemm_kernel<<<gg5, 256>>>(bt, pwp[2], pbp[2], b2, b0, D, D);
    dwconv_kernel<<<eblocks, 256>>>(b0, dwp[3], dbp[3], bt);
    gemm_kernel<<<gg5, 256>>>(bt, pwp[3], pbp[3], b0, b1, D, D);  // out3 = b1
    // attention
    gemm_kernel<<<ggq, 256>>>(b1, in_w, in_b, nullptr, qkvp, D3, D);
    attn_kernel<<<gga, 256>>>(qkvp, xm, bt);
    gemm_kernel<<<gg5, 256>>>(bt, out_w, out_b, b1, b2, D, D);    // out = proj + out3
    // ffc + residual -> final output
    gemm_kernel<<<gg5, 256>>>(b2, ffc_w, ffc_b, b2, outp, D, D);
}

// round 3
// speedup vs baseline: 1.7790x; 1.7790x over previous
#include <cuda_runtime.h>
#include <cstdint>
#include <cstddef>

#define B 32
#define T 512
#define D 500
#define H 10
#define HD 50
#define D3 1500
#define BT (B*T)
#define BTD (BT*D)
#define KW 7

// ---------------- scratch (static device arrays; no runtime allocation) ----
__device__ float g_b0[BTD];
__device__ float g_b1[BTD];
__device__ float g_b2[BTD];
__device__ float g_bt[BTD];
__device__ float g_qkv[(size_t)BT * D3];

// ---------------- helpers ---------------------------------------------------
__device__ __forceinline__ uint32_t f2tf32(float x) {
    uint32_t r;
    asm("cvt.rna.tf32.f32 %0, %1;" : "=r"(r) : "f"(x));
    return r;
}

#define MMA_TF32(c, a, b) \
    asm volatile("mma.sync.aligned.m16n8k8.row.col.f32.tf32.tf32.f32 " \
        "{%0,%1,%2,%3}, {%4,%5,%6,%7}, {%8,%9}, {%0,%1,%2,%3};" \
        : "+f"((c)[0]), "+f"((c)[1]), "+f"((c)[2]), "+f"((c)[3]) \
        : "r"((a)[0]), "r"((a)[1]), "r"((a)[2]), "r"((a)[3]), \
          "r"((b)[0]), "r"((b)[1]))

// ---------------- positional embedding + add ------------------------------
__global__ void posemb_kernel(const int* __restrict__ ori,
                              const float* __restrict__ x,
                              float* __restrict__ out) {
    int idx = blockIdx.x * blockDim.x + threadIdx.x;
    if (idx >= BTD) return;
    int d  = idx % D;
    int bt = idx / D;
    int t  = bt % T;
    float pe = 0.f;
    if (ori[bt] != 0) {
        float pos = (float)(t + 1);
        int   i   = (d < 250) ? d : (d - 250);
        float ang = pos * expf((float)i * -0.036989318763f);
        pe = (d < 250) ? sinf(ang) : cosf(ang);
    }
    out[idx] = pe + x[idx];
}

// ---------------- depthwise conv1d (k=7, pad=3) ----------------------------
__global__ void dwconv_kernel(const float* __restrict__ x,
                              const float* __restrict__ w,
                              const float* __restrict__ bias,
                              float* __restrict__ y) {
    int idx = blockIdx.x * blockDim.x + threadIdx.x;
    if (idx >= BTD) return;
    int d  = idx % D;
    int bt = idx / D;
    int t  = bt % T;
    int b  = bt / T;
    const float* wd = w + d * KW;
    float acc = bias[d];
    const float* xb = x + (size_t)(b * T) * D + d;
#pragma unroll
    for (int j = 0; j < KW; j++) {
        int tt = t + j - 3;
        if (tt >= 0 && tt < T) acc = fmaf(wd[j], xb[(size_t)tt * D], acc);
    }
    y[idx] = acc;
}

// =================== tf32 warp-mma GEMM ====================================
// C[M,N] = A[M,Kd] * W[N,Kd]^T + bias (+res). Tile 128x128, K-chunks of 32.
// 8 warps, each 64x32 (4x4 tiles of m16n8k8). Smem pitch 36 -> conflict-free
// fragment loads (bank = 4*(lane>>2) + (lane&3) + const, all distinct).
#define GBM 128
#define GBN 128
#define GBK 32
#define SPITCH 36

__global__ __launch_bounds__(256)
void gemm_mma(const float* __restrict__ A, const float* __restrict__ W,
              const float* __restrict__ bias, const float* __restrict__ res,
              float* __restrict__ C, int N, int Kd) {
    __shared__ uint32_t As[GBM][SPITCH];
    __shared__ uint32_t Bs[GBN][SPITCH];

    int tid  = threadIdx.x;
    int lane = tid & 31, wid = tid >> 5;
    int g = lane >> 2, t = lane & 3;
    int m0 = blockIdx.y * GBM;
    int n0 = blockIdx.x * GBN;
    int wm = (wid & 1) * 64;    // warp m offset in tile
    int wn = (wid >> 1) * 32;   // warp n offset in tile

    float acc[4][4][4];
#pragma unroll
    for (int mt = 0; mt < 4; mt++)
#pragma unroll
        for (int nt = 0; nt < 4; nt++)
#pragma unroll
            for (int i = 0; i < 4; i++) acc[mt][nt][i] = 0.f;

    const int KT = (Kd + GBK - 1) / GBK;
    for (int kt = 0; kt < KT; kt++) {
        int k0 = kt * GBK;
        // stage A: 128 rows x 8 float4-groups, 4 iters of 256 threads
#pragma unroll
        for (int i = 0; i < 4; i++) {
            int idx = i * 256 + tid;
            int r  = idx >> 3;
            int kg = idx & 7;
            int k  = k0 + kg * 4;
            float4 v = make_float4(0.f, 0.f, 0.f, 0.f);
            if (k < Kd) v = *(const float4*)(A + (size_t)(m0 + r) * Kd + k);
            As[r][kg * 4 + 0] = f2tf32(v.x);
            As[r][kg * 4 + 1] = f2tf32(v.y);
            As[r][kg * 4 + 2] = f2tf32(v.z);
            As[r][kg * 4 + 3] = f2tf32(v.w);
        }
        // stage B (= W rows)
#pragma unroll
        for (int i = 0; i < 4; i++) {
            int idx = i * 256 + tid;
            int r  = idx >> 3;
            int kg = idx & 7;
            int k  = k0 + kg * 4;
            int n  = n0 + r;
            float4 v = make_float4(0.f, 0.f, 0.f, 0.f);
            if (k < Kd && n < N) v = *(const float4*)(W + (size_t)n * Kd + k);
            Bs[r][kg * 4 + 0] = f2tf32(v.x);
            Bs[r][kg * 4 + 1] = f2tf32(v.y);
            Bs[r][kg * 4 + 2] = f2tf32(v.z);
            Bs[r][kg * 4 + 3] = f2tf32(v.w);
        }
        __syncthreads();

#pragma unroll
        for (int ks = 0; ks < 4; ks++) {
            int kk = ks * 8;
            uint32_t af[4][4], bf[4][2];
#pragma unroll
            for (int mt = 0; mt < 4; mt++) {
                int mr = wm + mt * 16 + g;
                af[mt][0] = As[mr][kk + t];
                af[mt][1] = As[mr + 8][kk + t];
                af[mt][2] = As[mr][kk + t + 4];
                af[mt][3] = As[mr + 8][kk + t + 4];
            }
#pragma unroll
            for (int nt = 0; nt < 4; nt++) {
                int nc = wn + nt * 8 + g;
                bf[nt][0] = Bs[nc][kk + t];
                bf[nt][1] = Bs[nc][kk + t + 4];
            }
#pragma unroll
            for (int mt = 0; mt < 4; mt++)
#pragma unroll
                for (int nt = 0; nt < 4; nt++)
                    MMA_TF32(acc[mt][nt], af[mt], bf[nt]);
        }
        __syncthreads();
    }

    // epilogue: bias + optional residual, float2 stores (cols even, N even)
#pragma unroll
    for (int mt = 0; mt < 4; mt++) {
        int row0 = m0 + wm + mt * 16 + g;
#pragma unroll
        for (int nt = 0; nt < 4; nt++) {
            int col = n0 + wn + nt * 8 + 2 * t;
            if (col < N) {
                float2 bv = *(const float2*)(bias + col);
                float2 o0, o1;
                o0.x = acc[mt][nt][0] + bv.x;
                o0.y = acc[mt][nt][1] + bv.y;
                o1.x = acc[mt][nt][2] + bv.x;
                o1.y = acc[mt][nt][3] + bv.y;
                size_t i0 = (size_t)row0 * N + col;
                size_t i1 = (size_t)(row0 + 8) * N + col;
                if (res) {
                    float2 r0 = *(const float2*)(res + i0);
                    float2 r1 = *(const float2*)(res + i1);
                    o0.x += r0.x; o0.y += r0.y;
                    o1.x += r1.x; o1.y += r1.y;
                }
                *(float2*)(C + i0) = o0;
                *(float2*)(C + i1) = o1;
            }
        }
    }
}

// ---------------- fused flash attention ------------------------------------
#define QT 64
#define KTL 64
#define SP 64

__global__ __launch_bounds__(256)
void attn_kernel(const float* __restrict__ qkv,
                 const unsigned char* __restrict__ mask,
                 float* __restrict__ out) {
    __shared__ float Qt[HD][SP];
    __shared__ float KtS[KTL][SP];
    __shared__ float Vs[KTL][SP];
    __shared__ float corr_s[QT];
    __shared__ float l_s[QT];
    __shared__ unsigned char msk[KTL];

    int tid = threadIdx.x;
    int bh  = blockIdx.y;
    int b   = bh / H, h = bh % H;
    int q0  = blockIdx.x * QT;
    int ty  = tid >> 4, tx = tid & 15;
    const float scale = 0.14142135623730951f;

    const float* qbase = qkv + (size_t)(b * T + q0) * D3 + h * HD;
    for (int idx = tid; idx < QT * HD; idx += 256) {
        int i = idx / HD, d = idx % HD;
        Qt[d][i] = qbase[(size_t)i * D3 + d] * scale;
    }
    for (int idx = tid; idx < KTL * (SP - HD); idx += 256) {
        int j = idx / (SP - HD), c = HD + idx % (SP - HD);
        Vs[j][c] = 0.f;
    }

    float o[4][4];
#pragma unroll
    for (int i = 0; i < 4; i++)
#pragma unroll
        for (int j = 0; j < 4; j++) o[i][j] = 0.f;
    float m_i = -1e30f, l_i = 0.f;

    for (int kt = 0; kt < T / KTL; kt++) {
        int k0 = kt * KTL;
        __syncthreads();
        const float* kbase = qkv + (size_t)(b * T + k0) * D3 + D + h * HD;
        const float* vbase = kbase + D;
        for (int idx = tid; idx < KTL * HD; idx += 256) {
            int j = idx / HD, d = idx % HD;
            KtS[d][j] = kbase[(size_t)j * D3 + d];
            Vs[j][d]  = vbase[(size_t)j * D3 + d];
        }
        if (tid < KTL) msk[tid] = mask[b * T + k0 + tid];
        __syncthreads();

        float s[4][4];
#pragma unroll
        for (int i = 0; i < 4; i++)
#pragma unroll
            for (int j = 0; j < 4; j++) s[i][j] = 0.f;
#pragma unroll
        for (int d = 0; d < HD; d++) {
            float4 aq = *(const float4*)&Qt[d][ty * 4];
            float4 bk = *(const float4*)&KtS[d][tx * 4];
            float qa[4] = {aq.x, aq.y, aq.z, aq.w};
            float kb[4] = {bk.x, bk.y, bk.z, bk.w};
#pragma unroll
            for (int i = 0; i < 4; i++)
#pragma unroll
                for (int j = 0; j < 4; j++)
                    s[i][j] = fmaf(qa[i], kb[j], s[i][j]);
        }
        __syncthreads();

#pragma unroll
        for (int jj = 0; jj < 4; jj++) {
            int j = tx * 4 + jj;
            bool mk = (msk[j] != 0);
            float4 v;
            v.x = mk ? -1e30f : s[0][jj];
            v.y = mk ? -1e30f : s[1][jj];
            v.z = mk ? -1e30f : s[2][jj];
            v.w = mk ? -1e30f : s[3][jj];
            *(float4*)&KtS[j][ty * 4] = v;
        }
        __syncthreads();

        if (tid < QT) {
            int i = tid;
            float tmax = -1e30f;
#pragma unroll 8
            for (int j = 0; j < KTL; j++) tmax = fmaxf(tmax, KtS[j][i]);
            float mnew = fmaxf(m_i, tmax);
            float c = expf(m_i - mnew);
            float ls = 0.f;
#pragma unroll 8
            for (int j = 0; j < KTL; j++) {
                float p = expf(KtS[j][i] - mnew);
                KtS[j][i] = p;
                ls += p;
            }
            l_i = l_i * c + ls;
            m_i = mnew;
            corr_s[i] = c;
            l_s[i] = l_i;
        }
        __syncthreads();

#pragma unroll
        for (int i = 0; i < 4; i++) {
            float c = corr_s[ty * 4 + i];
#pragma unroll
            for (int j = 0; j < 4; j++) o[i][j] *= c;
        }
#pragma unroll 8
        for (int j = 0; j < KTL; j++) {
            float4 p4 = *(const float4*)&KtS[j][ty * 4];
            float4 v4 = *(const float4*)&Vs[j][tx * 4];
            float pa[4] = {p4.x, p4.y, p4.z, p4.w};
            float vb[4] = {v4.x, v4.y, v4.z, v4.w};
#pragma unroll
            for (int i = 0; i < 4; i++)
#pragma unroll
                for (int jj = 0; jj < 4; jj++)
                    o[i][jj] = fmaf(pa[i], vb[jj], o[i][jj]);
        }
    }

    float* obase = out + (size_t)(b * T + q0) * D + h * HD;
#pragma unroll
    for (int i = 0; i < 4; i++) {
        int row = ty * 4 + i;
        float inv = 1.f / l_s[row];
#pragma unroll
        for (int j = 0; j < 4; j++) {
            int c = tx * 4 + j;
            if (c < HD) obase[(size_t)row * D + c] = o[i][j] * inv;
        }
    }
}

// ---------------- launch ----------------------------------------------------
extern "C" void kernel_launch(void* const* d_in, const int* in_sizes, int n_in,
                              void* d_out, int out_size) {
    const int* ori            = (const int*)d_in[0];
    const float* x            = (const float*)d_in[1];
    const unsigned char* xm   = (const unsigned char*)d_in[2];
    const float *dwp[4], *dbp[4], *pwp[4], *pbp[4];
    for (int i = 0; i < 4; i++) {
        dwp[i] = (const float*)d_in[3 + 4 * i];
        dbp[i] = (const float*)d_in[4 + 4 * i];
        pwp[i] = (const float*)d_in[5 + 4 * i];
        pbp[i] = (const float*)d_in[6 + 4 * i];
    }
    const float* in_w  = (const float*)d_in[19];
    const float* in_b  = (const float*)d_in[20];
    const float* out_w = (const float*)d_in[21];
    const float* out_b = (const float*)d_in[22];
    const float* ffc_w = (const float*)d_in[23];
    const float* ffc_b = (const float*)d_in[24];
    float* outp = (float*)d_out;

    float *b0, *b1, *b2, *bt, *qkvp;
    cudaGetSymbolAddress((void**)&b0,   g_b0);
    cudaGetSymbolAddress((void**)&b1,   g_b1);
    cudaGetSymbolAddress((void**)&b2,   g_b2);
    cudaGetSymbolAddress((void**)&bt,   g_bt);
    cudaGetSymbolAddress((void**)&qkvp, g_qkv);

    int eblocks = (BTD + 255) / 256;
    dim3 gg5((D + GBN - 1) / GBN, BT / GBM);    // (4, 128)
    dim3 ggq((D3 + GBN - 1) / GBN, BT / GBM);   // (12, 128)
    dim3 gga(T / QT, B * H);                    // (8, 320)

    posemb_kernel<<<eblocks, 256>>>(ori, x, b0);
    dwconv_kernel<<<eblocks, 256>>>(b0, dwp[0], dbp[0], bt);
    gemm_mma<<<gg5, 256>>>(bt, pwp[0], pbp[0], b0, b1, D, D);
    dwconv_kernel<<<eblocks, 256>>>(b1, dwp[1], dbp[1], bt);
    gemm_mma<<<gg5, 256>>>(bt, pwp[1], pbp[1], b1, b2, D, D);
    dwconv_kernel<<<eblocks, 256>>>(b2, dwp[2], dbp[2], bt);
    gemm_mma<<<gg5, 256>>>(bt, pwp[2], pbp[2], b2, b0, D, D);
    dwconv_kernel<<<eblocks, 256>>>(b0, dwp[3], dbp[3], bt);
    gemm_mma<<<gg5, 256>>>(bt, pwp[3], pbp[3], b0, b1, D, D);      // out3 = b1
    gemm_mma<<<ggq, 256>>>(b1, in_w, in_b, nullptr, qkvp, D3, D);  // qkv
    attn_kernel<<<gga, 256>>>(qkvp, xm, bt);
    gemm_mma<<<gg5, 256>>>(bt, out_w, out_b, b1, b2, D, D);        // + out3
    gemm_mma<<<gg5, 256>>>(b2, ffc_w, ffc_b, b2, outp, D, D);      // ffc + res
}

// round 4
// speedup vs baseline: 2.3330x; 1.3114x over previous
#include <cuda_runtime.h>
#include <cstdint>
#include <cstddef>

#define B 32
#define T 512
#define D 500
#define H 10
#define HD 50
#define D3 1500
#define BT (B*T)
#define BTD (BT*D)
#define KW 7

// ---------------- scratch (static device arrays; no runtime allocation) ----
__device__ float g_b0[BTD];
__device__ float g_b1[BTD];
__device__ float g_b2[BTD];
__device__ float g_bt[BTD];
__device__ float g_qkv[(size_t)BT * D3];

// ---------------- helpers ---------------------------------------------------
__device__ __forceinline__ uint32_t f2tf32(float x) {
    uint32_t r;
    asm("cvt.rna.tf32.f32 %0, %1;" : "=r"(r) : "f"(x));
    return r;
}

#define MMA_TF32(c, a, b) \
    asm volatile("mma.sync.aligned.m16n8k8.row.col.f32.tf32.tf32.f32 " \
        "{%0,%1,%2,%3}, {%4,%5,%6,%7}, {%8,%9}, {%0,%1,%2,%3};" \
        : "+f"((c)[0]), "+f"((c)[1]), "+f"((c)[2]), "+f"((c)[3]) \
        : "r"((a)[0]), "r"((a)[1]), "r"((a)[2]), "r"((a)[3]), \
          "r"((b)[0]), "r"((b)[1]))

// ---------------- positional embedding + add ------------------------------
__global__ void posemb_kernel(const int* __restrict__ ori,
                              const float* __restrict__ x,
                              float* __restrict__ out) {
    int idx = blockIdx.x * blockDim.x + threadIdx.x;
    if (idx >= BTD) return;
    int d  = idx % D;
    int bt = idx / D;
    int t  = bt % T;
    float pe = 0.f;
    if (ori[bt] != 0) {
        float pos = (float)(t + 1);
        int   i   = (d < 250) ? d : (d - 250);
        float ang = pos * expf((float)i * -0.036989318763f);
        pe = (d < 250) ? sinf(ang) : cosf(ang);
    }
    out[idx] = pe + x[idx];
}

// ---------------- depthwise conv1d (k=7, pad=3) ----------------------------
__global__ void dwconv_kernel(const float* __restrict__ x,
                              const float* __restrict__ w,
                              const float* __restrict__ bias,
                              float* __restrict__ y) {
    int idx = blockIdx.x * blockDim.x + threadIdx.x;
    if (idx >= BTD) return;
    int d  = idx % D;
    int bt = idx / D;
    int t  = bt % T;
    int b  = bt / T;
    const float* wd = w + d * KW;
    float acc = bias[d];
    const float* xb = x + (size_t)(b * T) * D + d;
#pragma unroll
    for (int j = 0; j < KW; j++) {
        int tt = t + j - 3;
        if (tt >= 0 && tt < T) acc = fmaf(wd[j], xb[(size_t)tt * D], acc);
    }
    y[idx] = acc;
}

// =================== tf32 warp-mma GEMM ====================================
#define GBM 128
#define GBN 128
#define GBK 32
#define SPITCH 36

__global__ __launch_bounds__(256)
void gemm_mma(const float* __restrict__ A, const float* __restrict__ W,
              const float* __restrict__ bias, const float* __restrict__ res,
              float* __restrict__ C, int N, int Kd) {
    __shared__ uint32_t As[GBM][SPITCH];
    __shared__ uint32_t Bs[GBN][SPITCH];

    int tid  = threadIdx.x;
    int lane = tid & 31, wid = tid >> 5;
    int g = lane >> 2, t = lane & 3;
    int m0 = blockIdx.y * GBM;
    int n0 = blockIdx.x * GBN;
    int wm = (wid & 1) * 64;
    int wn = (wid >> 1) * 32;

    float acc[4][4][4];
#pragma unroll
    for (int mt = 0; mt < 4; mt++)
#pragma unroll
        for (int nt = 0; nt < 4; nt++)
#pragma unroll
            for (int i = 0; i < 4; i++) acc[mt][nt][i] = 0.f;

    const int KT = (Kd + GBK - 1) / GBK;
    for (int kt = 0; kt < KT; kt++) {
        int k0 = kt * GBK;
#pragma unroll
        for (int i = 0; i < 4; i++) {
            int idx = i * 256 + tid;
            int r  = idx >> 3;
            int kg = idx & 7;
            int k  = k0 + kg * 4;
            float4 v = make_float4(0.f, 0.f, 0.f, 0.f);
            if (k < Kd) v = *(const float4*)(A + (size_t)(m0 + r) * Kd + k);
            As[r][kg * 4 + 0] = f2tf32(v.x);
            As[r][kg * 4 + 1] = f2tf32(v.y);
            As[r][kg * 4 + 2] = f2tf32(v.z);
            As[r][kg * 4 + 3] = f2tf32(v.w);
        }
#pragma unroll
        for (int i = 0; i < 4; i++) {
            int idx = i * 256 + tid;
            int r  = idx >> 3;
            int kg = idx & 7;
            int k  = k0 + kg * 4;
            int n  = n0 + r;
            float4 v = make_float4(0.f, 0.f, 0.f, 0.f);
            if (k < Kd && n < N) v = *(const float4*)(W + (size_t)n * Kd + k);
            Bs[r][kg * 4 + 0] = f2tf32(v.x);
            Bs[r][kg * 4 + 1] = f2tf32(v.y);
            Bs[r][kg * 4 + 2] = f2tf32(v.z);
            Bs[r][kg * 4 + 3] = f2tf32(v.w);
        }
        __syncthreads();

#pragma unroll
        for (int ks = 0; ks < 4; ks++) {
            int kk = ks * 8;
            uint32_t af[4][4], bf[4][2];
#pragma unroll
            for (int mt = 0; mt < 4; mt++) {
                int mr = wm + mt * 16 + g;
                af[mt][0] = As[mr][kk + t];
                af[mt][1] = As[mr + 8][kk + t];
                af[mt][2] = As[mr][kk + t + 4];
                af[mt][3] = As[mr + 8][kk + t + 4];
            }
#pragma unroll
            for (int nt = 0; nt < 4; nt++) {
                int nc = wn + nt * 8 + g;
                bf[nt][0] = Bs[nc][kk + t];
                bf[nt][1] = Bs[nc][kk + t + 4];
            }
#pragma unroll
            for (int mt = 0; mt < 4; mt++)
#pragma unroll
                for (int nt = 0; nt < 4; nt++)
                    MMA_TF32(acc[mt][nt], af[mt], bf[nt]);
        }
        __syncthreads();
    }

#pragma unroll
    for (int mt = 0; mt < 4; mt++) {
        int row0 = m0 + wm + mt * 16 + g;
#pragma unroll
        for (int nt = 0; nt < 4; nt++) {
            int col = n0 + wn + nt * 8 + 2 * t;
            if (col < N) {
                float2 bv = *(const float2*)(bias + col);
                float2 o0, o1;
                o0.x = acc[mt][nt][0] + bv.x;
                o0.y = acc[mt][nt][1] + bv.y;
                o1.x = acc[mt][nt][2] + bv.x;
                o1.y = acc[mt][nt][3] + bv.y;
                size_t i0 = (size_t)row0 * N + col;
                size_t i1 = (size_t)(row0 + 8) * N + col;
                if (res) {
                    float2 r0 = *(const float2*)(res + i0);
                    float2 r1 = *(const float2*)(res + i1);
                    o0.x += r0.x; o0.y += r0.y;
                    o1.x += r1.x; o1.y += r1.y;
                }
                *(float2*)(C + i0) = o0;
                *(float2*)(C + i1) = o1;
            }
        }
    }
}

// =================== tf32 warp-mma flash attention ==========================
// CTA: 128 q-rows of one (b,h). 8 warps, warp w owns q rows [w*16, w*16+16).
// KV tiles of 64. Contraction dims padded: HD->56 (QK), KV tile = 64 (PV).
// Smem pitches: Q/K 60, Vt/P 68 -> conflict-free fragment LDS.
#define AMQ 128
#define ANK 64
#define ADP 56
#define APQ 60
#define APV 68
#define ASM_BYTES ((AMQ*APQ + ANK*APQ + ADP*APV + AMQ*APV) * 4 + 64)

__global__ __launch_bounds__(256, 2)
void attn_mma(const float* __restrict__ qkv,
              const unsigned char* __restrict__ mask,
              float* __restrict__ out) {
    extern __shared__ uint32_t dsm[];
    uint32_t* Qs = dsm;                    // [128][60]
    uint32_t* Ks = Qs + AMQ * APQ;         // [64][60]
    uint32_t* Vt = Ks + ANK * APQ;         // [56][68]  (d, j)
    uint32_t* Ps = Vt + ADP * APV;         // [128][68]
    unsigned char* msk = (unsigned char*)(Ps + AMQ * APV);

    int tid  = threadIdx.x;
    int lane = tid & 31, wid = tid >> 5;
    int g = lane >> 2, t = lane & 3;
    int bh = blockIdx.y;
    int b  = bh / H, h = bh % H;
    int q0 = blockIdx.x * AMQ;
    const float scale = 0.14142135623730951f;

    // load Q tile (pre-scaled, pad d 50..55 with 0)
    const float* qbase = qkv + (size_t)(b * T + q0) * D3 + h * HD;
    for (int idx = tid; idx < AMQ * ADP; idx += 256) {
        int r = idx / ADP, d = idx - r * ADP;
        float v = (d < HD) ? qbase[(size_t)r * D3 + d] * scale : 0.f;
        Qs[r * APQ + d] = f2tf32(v);
    }

    int wq = wid * 16;
    const uint32_t* QA = Qs + (wq + g) * APQ;
    const uint32_t* QB = Qs + (wq + g + 8) * APQ;
    uint32_t* PsA = Ps + (wq + g) * APV;
    uint32_t* PsB = Ps + (wq + g + 8) * APV;

    float m0 = -1e30f, m1 = -1e30f, l0 = 0.f, l1 = 0.f;
    float oacc[7][4];
#pragma unroll
    for (int nt = 0; nt < 7; nt++)
#pragma unroll
        for (int i = 0; i < 4; i++) oacc[nt][i] = 0.f;

    for (int kt = 0; kt < T / ANK; kt++) {
        int k0 = kt * ANK;
        __syncthreads();   // prev PV done (iter 0: no-op ordering)
        const float* kbase = qkv + (size_t)(b * T + k0) * D3 + D + h * HD;
        const float* vbase = kbase + D;
        for (int idx = tid; idx < ANK * ADP; idx += 256) {
            int j = idx / ADP, d = idx - j * ADP;
            float kv = (d < HD) ? kbase[(size_t)j * D3 + d] : 0.f;
            float vv = (d < HD) ? vbase[(size_t)j * D3 + d] : 0.f;
            Ks[j * APQ + d] = f2tf32(kv);
            Vt[d * APV + j] = f2tf32(vv);
        }
        if (tid < ANK) msk[tid] = mask[b * T + k0 + tid];
        __syncthreads();

        // ---- S = Q K^T : warp computes 16 x 64
        float sacc[8][4];
#pragma unroll
        for (int nt = 0; nt < 8; nt++)
#pragma unroll
            for (int i = 0; i < 4; i++) sacc[nt][i] = 0.f;
#pragma unroll
        for (int ks = 0; ks < 7; ks++) {
            int kk = ks * 8;
            uint32_t af[4] = {QA[kk + t], QB[kk + t], QA[kk + t + 4], QB[kk + t + 4]};
#pragma unroll
            for (int nt = 0; nt < 8; nt++) {
                const uint32_t* Kr = Ks + (nt * 8 + g) * APQ + kk;
                uint32_t bf[2] = {Kr[t], Kr[t + 4]};
                MMA_TF32(sacc[nt], af, bf);
            }
        }

        // ---- mask + online softmax (rows r0 = wq+g, r1 = wq+g+8)
        float mx0 = -1e30f, mx1 = -1e30f;
#pragma unroll
        for (int nt = 0; nt < 8; nt++) {
            int c = nt * 8 + 2 * t;
            if (msk[c])     { sacc[nt][0] = -1e30f; sacc[nt][2] = -1e30f; }
            if (msk[c + 1]) { sacc[nt][1] = -1e30f; sacc[nt][3] = -1e30f; }
            mx0 = fmaxf(mx0, fmaxf(sacc[nt][0], sacc[nt][1]));
            mx1 = fmaxf(mx1, fmaxf(sacc[nt][2], sacc[nt][3]));
        }
        mx0 = fmaxf(mx0, __shfl_xor_sync(0xffffffffu, mx0, 1));
        mx0 = fmaxf(mx0, __shfl_xor_sync(0xffffffffu, mx0, 2));
        mx1 = fmaxf(mx1, __shfl_xor_sync(0xffffffffu, mx1, 1));
        mx1 = fmaxf(mx1, __shfl_xor_sync(0xffffffffu, mx1, 2));
        float mn0 = fmaxf(m0, mx0), mn1 = fmaxf(m1, mx1);
        float c0 = __expf(m0 - mn0), c1 = __expf(m1 - mn1);
        float s0 = 0.f, s1 = 0.f;
#pragma unroll
        for (int nt = 0; nt < 8; nt++) {
            float p00 = __expf(sacc[nt][0] - mn0);
            float p01 = __expf(sacc[nt][1] - mn0);
            float p10 = __expf(sacc[nt][2] - mn1);
            float p11 = __expf(sacc[nt][3] - mn1);
            s0 += p00 + p01;
            s1 += p10 + p11;
            int c = nt * 8 + 2 * t;
            *(uint2*)(PsA + c) = make_uint2(f2tf32(p00), f2tf32(p01));
            *(uint2*)(PsB + c) = make_uint2(f2tf32(p10), f2tf32(p11));
        }
        s0 += __shfl_xor_sync(0xffffffffu, s0, 1);
        s0 += __shfl_xor_sync(0xffffffffu, s0, 2);
        s1 += __shfl_xor_sync(0xffffffffu, s1, 1);
        s1 += __shfl_xor_sync(0xffffffffu, s1, 2);
        l0 = l0 * c0 + s0; m0 = mn0;
        l1 = l1 * c1 + s1; m1 = mn1;
#pragma unroll
        for (int nt = 0; nt < 7; nt++) {
            oacc[nt][0] *= c0; oacc[nt][1] *= c0;
            oacc[nt][2] *= c1; oacc[nt][3] *= c1;
        }
        __syncwarp();   // P rows are warp-local

        // ---- O += P V : m16 x n56 x k64
#pragma unroll
        for (int ks = 0; ks < 8; ks++) {
            int kk = ks * 8;
            uint32_t af[4] = {PsA[kk + t], PsB[kk + t], PsA[kk + t + 4], PsB[kk + t + 4]};
#pragma unroll
            for (int nt = 0; nt < 7; nt++) {
                const uint32_t* Vr = Vt + (nt * 8 + g) * APV + kk;
                uint32_t bf[2] = {Vr[t], Vr[t + 4]};
                MMA_TF32(oacc[nt], af, bf);
            }
        }
    }

    // ---- epilogue: O / l, store cols < 50
    float inv0 = 1.f / l0, inv1 = 1.f / l1;
    int r0 = q0 + wq + g;
    float* o0 = out + (size_t)(b * T + r0) * D + h * HD;
    float* o1 = o0 + (size_t)8 * D;
#pragma unroll
    for (int nt = 0; nt < 7; nt++) {
        int c = nt * 8 + 2 * t;
        if (c < HD) {
            *(float2*)(o0 + c) = make_float2(oacc[nt][0] * inv0, oacc[nt][1] * inv0);
            *(float2*)(o1 + c) = make_float2(oacc[nt][2] * inv1, oacc[nt][3] * inv1);
        }
    }
}

// ---------------- launch ----------------------------------------------------
extern "C" void kernel_launch(void* const* d_in, const int* in_sizes, int n_in,
                              void* d_out, int out_size) {
    const int* ori            = (const int*)d_in[0];
    const float* x            = (const float*)d_in[1];
    const unsigned char* xm   = (const unsigned char*)d_in[2];
    const float *dwp[4], *dbp[4], *pwp[4], *pbp[4];
    for (int i = 0; i < 4; i++) {
        dwp[i] = (const float*)d_in[3 + 4 * i];
        dbp[i] = (const float*)d_in[4 + 4 * i];
        pwp[i] = (const float*)d_in[5 + 4 * i];
        pbp[i] = (const float*)d_in[6 + 4 * i];
    }
    const float* in_w  = (const float*)d_in[19];
    const float* in_b  = (const float*)d_in[20];
    const float* out_w = (const float*)d_in[21];
    const float* out_b = (const float*)d_in[22];
    const float* ffc_w = (const float*)d_in[23];
    const float* ffc_b = (const float*)d_in[24];
    float* outp = (float*)d_out;

    float *b0, *b1, *b2, *bt, *qkvp;
    cudaGetSymbolAddress((void**)&b0,   g_b0);
    cudaGetSymbolAddress((void**)&b1,   g_b1);
    cudaGetSymbolAddress((void**)&b2,   g_b2);
    cudaGetSymbolAddress((void**)&bt,   g_bt);
    cudaGetSymbolAddress((void**)&qkvp, g_qkv);

    cudaFuncSetAttribute(attn_mma, cudaFuncAttributeMaxDynamicSharedMemorySize,
                         ASM_BYTES);

    int eblocks = (BTD + 255) / 256;
    dim3 gg5((D + GBN - 1) / GBN, BT / GBM);    // (4, 128)
    dim3 ggq((D3 + GBN - 1) / GBN, BT / GBM);   // (12, 128)
    dim3 gga(T / AMQ, B * H);                   // (4, 320)

    posemb_kernel<<<eblocks, 256>>>(ori, x, b0);
    dwconv_kernel<<<eblocks, 256>>>(b0, dwp[0], dbp[0], bt);
    gemm_mma<<<gg5, 256>>>(bt, pwp[0], pbp[0], b0, b1, D, D);
    dwconv_kernel<<<eblocks, 256>>>(b1, dwp[1], dbp[1], bt);
    gemm_mma<<<gg5, 256>>>(bt, pwp[1], pbp[1], b1, b2, D, D);
    dwconv_kernel<<<eblocks, 256>>>(b2, dwp[2], dbp[2], bt);
    gemm_mma<<<gg5, 256>>>(bt, pwp[2], pbp[2], b2, b0, D, D);
    dwconv_kernel<<<eblocks, 256>>>(b0, dwp[3], dbp[3], bt);
    gemm_mma<<<gg5, 256>>>(bt, pwp[3], pbp[3], b0, b1, D, D);      // out3 = b1
    gemm_mma<<<ggq, 256>>>(b1, in_w, in_b, nullptr, qkvp, D3, D);  // qkv
    attn_mma<<<gga, 256, ASM_BYTES>>>(qkvp, xm, bt);
    gemm_mma<<<gg5, 256>>>(bt, out_w, out_b, b1, b2, D, D);        // + out3
    gemm_mma<<<gg5, 256>>>(b2, ffc_w, ffc_b, b2, outp, D, D);      // ffc + res
}

// round 5
// speedup vs baseline: 3.0087x; 1.2896x over previous
#include <cuda_runtime.h>
#include <cstdint>
#include <cstddef>

#define B 32
#define T 512
#define D 500
#define H 10
#define HD 50
#define D3 1500
#define BT (B*T)
#define BTD (BT*D)
#define KW 7

// ---------------- scratch (static device arrays; no runtime allocation) ----
__device__ float g_b0[BTD];
__device__ float g_b1[BTD];
__device__ float g_b2[BTD];
__device__ float g_bt[BTD];
__device__ float g_b1t[BTD];          // tf32-rounded copy of out3
__device__ float g_b2t[BTD];          // tf32-rounded copy of out_proj result
__device__ float g_qkv[(size_t)BT * D3];
__device__ float g_wt[6 * D * D + D3 * D];   // rounded weights

// ---------------- helpers ---------------------------------------------------
__device__ __forceinline__ uint32_t f2tf32(float x) {
    uint32_t r;
    asm("cvt.rna.tf32.f32 %0, %1;" : "=r"(r) : "f"(x));
    return r;
}
__device__ __forceinline__ uint32_t smem_u32(const void* p) {
    uint32_t a;
    asm("{ .reg .u64 t; cvta.to.shared.u64 t, %1; cvt.u32.u64 %0, t; }" : "=r"(a) : "l"(p));
    return a;
}

#define MMA_TF32(c, a, b) \
    asm volatile("mma.sync.aligned.m16n8k8.row.col.f32.tf32.tf32.f32 " \
        "{%0,%1,%2,%3}, {%4,%5,%6,%7}, {%8,%9}, {%0,%1,%2,%3};" \
        : "+f"((c)[0]), "+f"((c)[1]), "+f"((c)[2]), "+f"((c)[3]) \
        : "r"((a)[0]), "r"((a)[1]), "r"((a)[2]), "r"((a)[3]), \
          "r"((b)[0]), "r"((b)[1]))

// ---------------- weight tf32 pre-round ------------------------------------
__global__ void cvt_kernel(const float* __restrict__ w, uint32_t* __restrict__ o, int n) {
    int i = blockIdx.x * blockDim.x + threadIdx.x;
    if (i < n) o[i] = f2tf32(w[i]);
}

// ---------------- positional embedding + add ------------------------------
__global__ void posemb_kernel(const int* __restrict__ ori,
                              const float* __restrict__ x,
                              float* __restrict__ out) {
    int idx = blockIdx.x * blockDim.x + threadIdx.x;
    if (idx >= BTD) return;
    int d  = idx % D;
    int bt = idx / D;
    int t  = bt % T;
    float pe = 0.f;
    if (ori[bt] != 0) {
        float pos = (float)(t + 1);
        int   i   = (d < 250) ? d : (d - 250);
        float ang = pos * expf((float)i * -0.036989318763f);
        pe = (d < 250) ? sinf(ang) : cosf(ang);
    }
    out[idx] = pe + x[idx];
}

// ---------------- depthwise conv1d (k=7, pad=3), float4, tf32-rounded out --
__global__ void dwconv4_kernel(const float* __restrict__ x,
                               const float* __restrict__ w,
                               const float* __restrict__ bias,
                               uint32_t* __restrict__ y) {
    int idx = blockIdx.x * blockDim.x + threadIdx.x;
    if (idx >= BTD / 4) return;
    int d4 = idx % (D / 4);
    int bt = idx / (D / 4);
    int t  = bt % T;
    int b  = bt / T;
    int d  = d4 * 4;
    float4 bv = *(const float4*)(bias + d);
    float a0 = bv.x, a1 = bv.y, a2 = bv.z, a3 = bv.w;
    const float* xb = x + (size_t)(b * T) * D + d;
#pragma unroll
    for (int j = 0; j < KW; j++) {
        int tt = t + j - 3;
        if (tt >= 0 && tt < T) {
            float4 v = *(const float4*)(xb + (size_t)tt * D);
            a0 = fmaf(w[(d + 0) * KW + j], v.x, a0);
            a1 = fmaf(w[(d + 1) * KW + j], v.y, a1);
            a2 = fmaf(w[(d + 2) * KW + j], v.z, a2);
            a3 = fmaf(w[(d + 3) * KW + j], v.w, a3);
        }
    }
    *(uint4*)(y + (size_t)idx * 4) =
        make_uint4(f2tf32(a0), f2tf32(a1), f2tf32(a2), f2tf32(a3));
}

// =================== pipelined tf32 warp-mma GEMM ===========================
// A and W must be tf32-pre-rounded fp32. cp.async double-buffered staging.
#define GBM 128
#define GBN 128
#define GBK 32
#define SPITCH 36
#define GBUF ((GBM + GBN) * SPITCH)
#define GSM_BYTES (2 * GBUF * 4)

__global__ __launch_bounds__(256, 2)
void gemm_pipe(const float* __restrict__ A, const float* __restrict__ W,
               const float* __restrict__ bias, const float* __restrict__ res,
               float* __restrict__ C, uint32_t* __restrict__ Ct, int N, int Kd) {
    extern __shared__ uint32_t sm[];

    int tid  = threadIdx.x;
    int lane = tid & 31, wid = tid >> 5;
    int g = lane >> 2, t = lane & 3;
    int m0 = blockIdx.y * GBM;
    int n0 = blockIdx.x * GBN;
    int wm = (wid & 1) * 64;
    int wn = (wid >> 1) * 32;

    // staging geometry: thread -> rows r0+{0,32,64,96}, k-group kg
    int r0 = tid >> 3, kg = tid & 7;
    uint32_t smbase = smem_u32(sm);
    uint32_t adst[4], bdst[4];
    const float* asrc[4];
    const float* bsrc[4];
    uint32_t bok[4];
#pragma unroll
    for (int i = 0; i < 4; i++) {
        int r = r0 + i * 32;
        adst[i] = smbase + (uint32_t)(r * SPITCH + kg * 4) * 4;
        bdst[i] = adst[i] + GBM * SPITCH * 4;
        asrc[i] = A + (size_t)(m0 + r) * Kd + kg * 4;
        int n = n0 + r;
        bok[i] = (n < N) ? 16u : 0u;
        bsrc[i] = W + (size_t)((n < N) ? n : 0) * Kd + kg * 4;
    }

    float acc[4][4][4];
#pragma unroll
    for (int mt = 0; mt < 4; mt++)
#pragma unroll
        for (int nt = 0; nt < 4; nt++)
#pragma unroll
            for (int i = 0; i < 4; i++) acc[mt][nt][i] = 0.f;

    const int KT = (Kd + GBK - 1) / GBK;

    // prologue: stage chunk 0 into buffer 0
    {
        int k = kg * 4;
        uint32_t kin = (k < Kd) ? 16u : 0u;
#pragma unroll
        for (int i = 0; i < 4; i++) {
            const float* sa = kin ? asrc[i] : A;
            asm volatile("cp.async.ca.shared.global [%0], [%1], 16, %2;"
                         :: "r"(adst[i]), "l"(sa), "r"(kin) : "memory");
            uint32_t bb = kin & bok[i];
            const float* sb = bb ? bsrc[i] : W;
            asm volatile("cp.async.ca.shared.global [%0], [%1], 16, %2;"
                         :: "r"(bdst[i]), "l"(sb), "r"(bb) : "memory");
        }
        asm volatile("cp.async.commit_group;" ::: "memory");
    }

    for (int kt = 0; kt < KT; kt++) {
        int buf = kt & 1;
        if (kt + 1 < KT) {
            int k0 = (kt + 1) * GBK;
            int k = k0 + kg * 4;
            uint32_t kin = (k < Kd) ? 16u : 0u;
            uint32_t bo = (buf ^ 1) ? (uint32_t)GBUF * 4 : 0u;
#pragma unroll
            for (int i = 0; i < 4; i++) {
                const float* sa = kin ? (asrc[i] + k0) : A;
                asm volatile("cp.async.ca.shared.global [%0], [%1], 16, %2;"
                             :: "r"(adst[i] + bo), "l"(sa), "r"(kin) : "memory");
                uint32_t bb = kin & bok[i];
                const float* sb = bb ? (bsrc[i] + k0) : W;
                asm volatile("cp.async.ca.shared.global [%0], [%1], 16, %2;"
                             :: "r"(bdst[i] + bo), "l"(sb), "r"(bb) : "memory");
            }
            asm volatile("cp.async.commit_group;" ::: "memory");
            asm volatile("cp.async.wait_group 1;" ::: "memory");
        } else {
            asm volatile("cp.async.wait_group 0;" ::: "memory");
        }
        __syncthreads();

        const uint32_t* Ab = sm + (buf ? GBUF : 0);
        const uint32_t* Bb = Ab + GBM * SPITCH;
#pragma unroll
        for (int ks = 0; ks < 4; ks++) {
            int kk = ks * 8;
            uint32_t af[4][4], bf[4][2];
#pragma unroll
            for (int mt = 0; mt < 4; mt++) {
                const uint32_t* Ar = Ab + (wm + mt * 16 + g) * SPITCH + kk;
                af[mt][0] = Ar[t];
                af[mt][1] = Ar[8 * SPITCH + t];
                af[mt][2] = Ar[t + 4];
                af[mt][3] = Ar[8 * SPITCH + t + 4];
            }
#pragma unroll
            for (int nt = 0; nt < 4; nt++) {
                const uint32_t* Br = Bb + (wn + nt * 8 + g) * SPITCH + kk;
                bf[nt][0] = Br[t];
                bf[nt][1] = Br[t + 4];
            }
#pragma unroll
            for (int mt = 0; mt < 4; mt++)
#pragma unroll
                for (int nt = 0; nt < 4; nt++)
                    MMA_TF32(acc[mt][nt], af[mt], bf[nt]);
        }
        __syncthreads();
    }

    // epilogue: bias + optional residual; optional tf32-rounded copy
#pragma unroll
    for (int mt = 0; mt < 4; mt++) {
        int row0 = m0 + wm + mt * 16 + g;
#pragma unroll
        for (int nt = 0; nt < 4; nt++) {
            int col = n0 + wn + nt * 8 + 2 * t;
            if (col < N) {
                float2 bv = *(const float2*)(bias + col);
                float2 o0, o1;
                o0.x = acc[mt][nt][0] + bv.x;
                o0.y = acc[mt][nt][1] + bv.y;
                o1.x = acc[mt][nt][2] + bv.x;
                o1.y = acc[mt][nt][3] + bv.y;
                size_t i0 = (size_t)row0 * N + col;
                size_t i1 = (size_t)(row0 + 8) * N + col;
                if (res) {
                    float2 r0v = *(const float2*)(res + i0);
                    float2 r1v = *(const float2*)(res + i1);
                    o0.x += r0v.x; o0.y += r0v.y;
                    o1.x += r1v.x; o1.y += r1v.y;
                }
                *(float2*)(C + i0) = o0;
                *(float2*)(C + i1) = o1;
                if (Ct) {
                    *(uint2*)(Ct + i0) = make_uint2(f2tf32(o0.x), f2tf32(o0.y));
                    *(uint2*)(Ct + i1) = make_uint2(f2tf32(o1.x), f2tf32(o1.y));
                }
            }
        }
    }
}

// =================== tf32 warp-mma flash attention ==========================
#define AMQ 128
#define ANK 64
#define ADP 56
#define APQ 60
#define APV 68
#define ASM_BYTES ((AMQ*APQ + ANK*APQ + ADP*APV + AMQ*APV) * 4 + 64)

__global__ __launch_bounds__(256, 2)
void attn_mma(const float* __restrict__ qkv,
              const unsigned char* __restrict__ mask,
              uint32_t* __restrict__ out) {
    extern __shared__ uint32_t dsm[];
    uint32_t* Qs = dsm;
    uint32_t* Ks = Qs + AMQ * APQ;
    uint32_t* Vt = Ks + ANK * APQ;
    uint32_t* Ps = Vt + ADP * APV;
    unsigned char* msk = (unsigned char*)(Ps + AMQ * APV);

    int tid  = threadIdx.x;
    int lane = tid & 31, wid = tid >> 5;
    int g = lane >> 2, t = lane & 3;
    int bh = blockIdx.y;
    int b  = bh / H, h = bh % H;
    int q0 = blockIdx.x * AMQ;
    const float scale = 0.14142135623730951f;

    const float* qbase = qkv + (size_t)(b * T + q0) * D3 + h * HD;
    for (int idx = tid; idx < AMQ * ADP; idx += 256) {
        int r = idx / ADP, d = idx - r * ADP;
        float v = (d < HD) ? qbase[(size_t)r * D3 + d] * scale : 0.f;
        Qs[r * APQ + d] = f2tf32(v);
    }

    int wq = wid * 16;
    const uint32_t* QA = Qs + (wq + g) * APQ;
    const uint32_t* QB = Qs + (wq + g + 8) * APQ;
    uint32_t* PsA = Ps + (wq + g) * APV;
    uint32_t* PsB = Ps + (wq + g + 8) * APV;

    float m0 = -1e30f, m1 = -1e30f, l0 = 0.f, l1 = 0.f;
    float oacc[7][4];
#pragma unroll
    for (int nt = 0; nt < 7; nt++)
#pragma unroll
        for (int i = 0; i < 4; i++) oacc[nt][i] = 0.f;

    for (int kt = 0; kt < T / ANK; kt++) {
        int k0 = kt * ANK;
        __syncthreads();
        const float* kbase = qkv + (size_t)(b * T + k0) * D3 + D + h * HD;
        const float* vbase = kbase + D;
        for (int idx = tid; idx < ANK * ADP; idx += 256) {
            int j = idx / ADP, d = idx - j * ADP;
            float kv = (d < HD) ? kbase[(size_t)j * D3 + d] : 0.f;
            float vv = (d < HD) ? vbase[(size_t)j * D3 + d] : 0.f;
            Ks[j * APQ + d] = f2tf32(kv);
            Vt[d * APV + j] = f2tf32(vv);
        }
        if (tid < ANK) msk[tid] = mask[b * T + k0 + tid];
        __syncthreads();

        float sacc[8][4];
#pragma unroll
        for (int nt = 0; nt < 8; nt++)
#pragma unroll
            for (int i = 0; i < 4; i++) sacc[nt][i] = 0.f;
#pragma unroll
        for (int ks = 0; ks < 7; ks++) {
            int kk = ks * 8;
            uint32_t af[4] = {QA[kk + t], QB[kk + t], QA[kk + t + 4], QB[kk + t + 4]};
#pragma unroll
            for (int nt = 0; nt < 8; nt++) {
                const uint32_t* Kr = Ks + (nt * 8 + g) * APQ + kk;
                uint32_t bf[2] = {Kr[t], Kr[t + 4]};
                MMA_TF32(sacc[nt], af, bf);
            }
        }

        float mx0 = -1e30f, mx1 = -1e30f;
#pragma unroll
        for (int nt = 0; nt < 8; nt++) {
            int c = nt * 8 + 2 * t;
            if (msk[c])     { sacc[nt][0] = -1e30f; sacc[nt][2] = -1e30f; }
            if (msk[c + 1]) { sacc[nt][1] = -1e30f; sacc[nt][3] = -1e30f; }
            mx0 = fmaxf(mx0, fmaxf(sacc[nt][0], sacc[nt][1]));
            mx1 = fmaxf(mx1, fmaxf(sacc[nt][2], sacc[nt][3]));
        }
        mx0 = fmaxf(mx0, __shfl_xor_sync(0xffffffffu, mx0, 1));
        mx0 = fmaxf(mx0, __shfl_xor_sync(0xffffffffu, mx0, 2));
        mx1 = fmaxf(mx1, __shfl_xor_sync(0xffffffffu, mx1, 1));
        mx1 = fmaxf(mx1, __shfl_xor_sync(0xffffffffu, mx1, 2));
        float mn0 = fmaxf(m0, mx0), mn1 = fmaxf(m1, mx1);
        float c0 = __expf(m0 - mn0), c1 = __expf(m1 - mn1);
        float s0 = 0.f, s1 = 0.f;
#pragma unroll
        for (int nt = 0; nt < 8; nt++) {
            float p00 = __expf(sacc[nt][0] - mn0);
            float p01 = __expf(sacc[nt][1] - mn0);
            float p10 = __expf(sacc[nt][2] - mn1);
            float p11 = __expf(sacc[nt][3] - mn1);
            s0 += p00 + p01;
            s1 += p10 + p11;
            int c = nt * 8 + 2 * t;
            *(uint2*)(PsA + c) = make_uint2(f2tf32(p00), f2tf32(p01));
            *(uint2*)(PsB + c) = make_uint2(f2tf32(p10), f2tf32(p11));
        }
        s0 += __shfl_xor_sync(0xffffffffu, s0, 1);
        s0 += __shfl_xor_sync(0xffffffffu, s0, 2);
        s1 += __shfl_xor_sync(0xffffffffu, s1, 1);
        s1 += __shfl_xor_sync(0xffffffffu, s1, 2);
        l0 = l0 * c0 + s0; m0 = mn0;
        l1 = l1 * c1 + s1; m1 = mn1;
#pragma unroll
        for (int nt = 0; nt < 7; nt++) {
            oacc[nt][0] *= c0; oacc[nt][1] *= c0;
            oacc[nt][2] *= c1; oacc[nt][3] *= c1;
        }
        __syncwarp();

#pragma unroll
        for (int ks = 0; ks < 8; ks++) {
            int kk = ks * 8;
            uint32_t af[4] = {PsA[kk + t], PsB[kk + t], PsA[kk + t + 4], PsB[kk + t + 4]};
#pragma unroll
            for (int nt = 0; nt < 7; nt++) {
                const uint32_t* Vr = Vt + (nt * 8 + g) * APV + kk;
                uint32_t bf[2] = {Vr[t], Vr[t + 4]};
                MMA_TF32(oacc[nt], af, bf);
            }
        }
    }

    // epilogue: O / l, tf32-rounded (consumer is out_proj GEMM A)
    float inv0 = 1.f / l0, inv1 = 1.f / l1;
    int r0 = q0 + wq + g;
    uint32_t* o0 = out + (size_t)(b * T + r0) * D + h * HD;
    uint32_t* o1 = o0 + (size_t)8 * D;
#pragma unroll
    for (int nt = 0; nt < 7; nt++) {
        int c = nt * 8 + 2 * t;
        if (c < HD) {
            *(uint2*)(o0 + c) = make_uint2(f2tf32(oacc[nt][0] * inv0),
                                           f2tf32(oacc[nt][1] * inv0));
            *(uint2*)(o1 + c) = make_uint2(f2tf32(oacc[nt][2] * inv1),
                                           f2tf32(oacc[nt][3] * inv1));
        }
    }
}

// ---------------- launch ----------------------------------------------------
extern "C" void kernel_launch(void* const* d_in, const int* in_sizes, int n_in,
                              void* d_out, int out_size) {
    const int* ori            = (const int*)d_in[0];
    const float* x            = (const float*)d_in[1];
    const unsigned char* xm   = (const unsigned char*)d_in[2];
    const float *dwp[4], *dbp[4], *pwp[4], *pbp[4];
    for (int i = 0; i < 4; i++) {
        dwp[i] = (const float*)d_in[3 + 4 * i];
        dbp[i] = (const float*)d_in[4 + 4 * i];
        pwp[i] = (const float*)d_in[5 + 4 * i];
        pbp[i] = (const float*)d_in[6 + 4 * i];
    }
    const float* in_w  = (const float*)d_in[19];
    const float* in_b  = (const float*)d_in[20];
    const float* out_w = (const float*)d_in[21];
    const float* out_b = (const float*)d_in[22];
    const float* ffc_w = (const float*)d_in[23];
    const float* ffc_b = (const float*)d_in[24];
    float* outp = (float*)d_out;

    float *b0, *b1, *b2, *bt, *b1t, *b2t, *qkvp, *wt;
    cudaGetSymbolAddress((void**)&b0,   g_b0);
    cudaGetSymbolAddress((void**)&b1,   g_b1);
    cudaGetSymbolAddress((void**)&b2,   g_b2);
    cudaGetSymbolAddress((void**)&bt,   g_bt);
    cudaGetSymbolAddress((void**)&b1t,  g_b1t);
    cudaGetSymbolAddress((void**)&b2t,  g_b2t);
    cudaGetSymbolAddress((void**)&qkvp, g_qkv);
    cudaGetSymbolAddress((void**)&wt,   g_wt);

    cudaFuncSetAttribute(attn_mma, cudaFuncAttributeMaxDynamicSharedMemorySize, ASM_BYTES);
    cudaFuncSetAttribute(gemm_pipe, cudaFuncAttributeMaxDynamicSharedMemorySize, GSM_BYTES);

    // rounded weight segments
    float* wtp[4];
    for (int i = 0; i < 4; i++) wtp[i] = wt + i * D * D;
    float* wt_in  = wt + 4 * D * D;
    float* wt_out = wt + 4 * D * D + D3 * D;
    float* wt_ffc = wt_out + D * D;

    const int DD = D * D;
    for (int i = 0; i < 4; i++)
        cvt_kernel<<<(DD + 255) / 256, 256>>>(pwp[i], (uint32_t*)wtp[i], DD);
    cvt_kernel<<<(D3 * D + 255) / 256, 256>>>(in_w,  (uint32_t*)wt_in,  D3 * D);
    cvt_kernel<<<(DD + 255) / 256, 256>>>(out_w, (uint32_t*)wt_out, DD);
    cvt_kernel<<<(DD + 255) / 256, 256>>>(ffc_w, (uint32_t*)wt_ffc, DD);

    int eblocks  = (BTD + 255) / 256;
    int e4blocks = (BTD / 4 + 255) / 256;
    dim3 gg5((D + GBN - 1) / GBN, BT / GBM);    // (4, 128)
    dim3 ggq((D3 + GBN - 1) / GBN, BT / GBM);   // (12, 128)
    dim3 gga(T / AMQ, B * H);                   // (4, 320)

    posemb_kernel<<<eblocks, 256>>>(ori, x, b0);
    dwconv4_kernel<<<e4blocks, 256>>>(b0, dwp[0], dbp[0], (uint32_t*)bt);
    gemm_pipe<<<gg5, 256, GSM_BYTES>>>(bt, wtp[0], pbp[0], b0, b1, nullptr, D, D);
    dwconv4_kernel<<<e4blocks, 256>>>(b1, dwp[1], dbp[1], (uint32_t*)bt);
    gemm_pipe<<<gg5, 256, GSM_BYTES>>>(bt, wtp[1], pbp[1], b1, b2, nullptr, D, D);
    dwconv4_kernel<<<e4blocks, 256>>>(b2, dwp[2], dbp[2], (uint32_t*)bt);
    gemm_pipe<<<gg5, 256, GSM_BYTES>>>(bt, wtp[2], pbp[2], b2, b0, nullptr, D, D);
    dwconv4_kernel<<<e4blocks, 256>>>(b0, dwp[3], dbp[3], (uint32_t*)bt);
    gemm_pipe<<<gg5, 256, GSM_BYTES>>>(bt, wtp[3], pbp[3], b0, b1, (uint32_t*)b1t, D, D);
    gemm_pipe<<<ggq, 256, GSM_BYTES>>>(b1t, wt_in, in_b, nullptr, qkvp, nullptr, D3, D);
    attn_mma<<<gga, 256, ASM_BYTES>>>(qkvp, xm, (uint32_t*)bt);
    gemm_pipe<<<gg5, 256, GSM_BYTES>>>(bt, wt_out, out_b, b1, b2, (uint32_t*)b2t, D, D);
    gemm_pipe<<<gg5, 256, GSM_BYTES>>>(b2t, wt_ffc, ffc_b, b2, outp, nullptr, D, D);
}

// round 6
// speedup vs baseline: 3.2037x; 1.0648x over previous
#include <cuda_runtime.h>
#include <cstdint>
#include <cstddef>

#define B 32
#define T 512
#define D 500
#define H 10
#define HD 50
#define D3 1500
#define BT (B*T)
#define BTD (BT*D)
#define KW 7
#define QKVP 1920   // padded qkv row pitch: 3 * H * 64

// ---------------- scratch (static device arrays; no runtime allocation) ----
__device__ float g_b0[BTD];
__device__ float g_b1[BTD];
__device__ float g_b2[BTD];
__device__ float g_bt[BTD];
__device__ float g_b1t[BTD];
__device__ float g_b2t[BTD];
__device__ float g_qkv[(size_t)BT * QKVP];
__device__ float g_wt[6 * D * D + D3 * D];

// ---------------- helpers ---------------------------------------------------
__device__ __forceinline__ uint32_t f2tf32(float x) {
    uint32_t r;
    asm("cvt.rna.tf32.f32 %0, %1;" : "=r"(r) : "f"(x));
    return r;
}
__device__ __forceinline__ uint32_t smem_u32(const void* p) {
    uint32_t a;
    asm("{ .reg .u64 t; cvta.to.shared.u64 t, %1; cvt.u32.u64 %0, t; }" : "=r"(a) : "l"(p));
    return a;
}

#define MMA_TF32(c, a, b) \
    asm volatile("mma.sync.aligned.m16n8k8.row.col.f32.tf32.tf32.f32 " \
        "{%0,%1,%2,%3}, {%4,%5,%6,%7}, {%8,%9}, {%0,%1,%2,%3};" \
        : "+f"((c)[0]), "+f"((c)[1]), "+f"((c)[2]), "+f"((c)[3]) \
        : "r"((a)[0]), "r"((a)[1]), "r"((a)[2]), "r"((a)[3]), \
          "r"((b)[0]), "r"((b)[1]))

#define CP16(dst, src) \
    asm volatile("cp.async.ca.shared.global [%0], [%1], 16;" :: "r"(dst), "l"(src) : "memory")
#define CP8(dst, src) \
    asm volatile("cp.async.ca.shared.global [%0], [%1], 8;"  :: "r"(dst), "l"(src) : "memory")
#define CPCOMMIT() asm volatile("cp.async.commit_group;" ::: "memory")
#define CPWAIT0()  asm volatile("cp.async.wait_group 0;" ::: "memory")

// ---------------- merged weight tf32 pre-round -----------------------------
__global__ void cvt_all(const float* __restrict__ p0, const float* __restrict__ p1,
                        const float* __restrict__ p2, const float* __restrict__ p3,
                        const float* __restrict__ p4, const float* __restrict__ p5,
                        const float* __restrict__ p6, uint32_t* __restrict__ o) {
    const int DD = D * D;
    int i = blockIdx.x * blockDim.x + threadIdx.x;
    if (i >= 6 * DD + D3 * D) return;
    float v;
    if      (i < DD)              v = p0[i];
    else if (i < 2 * DD)          v = p1[i - DD];
    else if (i < 3 * DD)          v = p2[i - 2 * DD];
    else if (i < 4 * DD)          v = p3[i - 3 * DD];
    else if (i < 4 * DD + D3 * D) v = p4[i - 4 * DD];
    else if (i < 5 * DD + D3 * D) v = p5[i - 4 * DD - D3 * D];
    else                          v = p6[i - 5 * DD - D3 * D];
    o[i] = f2tf32(v);
}

// ---------------- positional embedding + add ------------------------------
__global__ void posemb_kernel(const int* __restrict__ ori,
                              const float* __restrict__ x,
                              float* __restrict__ out) {
    int idx = blockIdx.x * blockDim.x + threadIdx.x;
    if (idx >= BTD) return;
    int d  = idx % D;
    int bt = idx / D;
    int t  = bt % T;
    float pe = 0.f;
    if (ori[bt] != 0) {
        float pos = (float)(t + 1);
        int   i   = (d < 250) ? d : (d - 250);
        float ang = pos * expf((float)i * -0.036989318763f);
        pe = (d < 250) ? sinf(ang) : cosf(ang);
    }
    out[idx] = pe + x[idx];
}

// ---------------- depthwise conv1d (k=7, pad=3), float4, tf32-rounded out --
__global__ void dwconv4_kernel(const float* __restrict__ x,
                               const float* __restrict__ w,
                               const float* __restrict__ bias,
                               uint32_t* __restrict__ y) {
    int idx = blockIdx.x * blockDim.x + threadIdx.x;
    if (idx >= BTD / 4) return;
    int d4 = idx % (D / 4);
    int bt = idx / (D / 4);
    int t  = bt % T;
    int b  = bt / T;
    int d  = d4 * 4;
    float4 bv = *(const float4*)(bias + d);
    float a0 = bv.x, a1 = bv.y, a2 = bv.z, a3 = bv.w;
    const float* xb = x + (size_t)(b * T) * D + d;
#pragma unroll
    for (int j = 0; j < KW; j++) {
        int tt = t + j - 3;
        if (tt >= 0 && tt < T) {
            float4 v = *(const float4*)(xb + (size_t)tt * D);
            a0 = fmaf(w[(d + 0) * KW + j], v.x, a0);
            a1 = fmaf(w[(d + 1) * KW + j], v.y, a1);
            a2 = fmaf(w[(d + 2) * KW + j], v.z, a2);
            a3 = fmaf(w[(d + 3) * KW + j], v.w, a3);
        }
    }
    *(uint4*)(y + (size_t)idx * 4) =
        make_uint4(f2tf32(a0), f2tf32(a1), f2tf32(a2), f2tf32(a3));
}

// =================== pipelined tf32 warp-mma GEMM ===========================
// modes: 0 = C fp32 (+res); 1 = C fp32 (+res) + Ct tf32-rounded copy;
//        2 = head-padded tf32-rounded qkv output into C (res ignored)
#define GBM 128
#define GBN 128
#define GBK 32
#define SPITCH 36
#define GBUF ((GBM + GBN) * SPITCH)
#define GSM_BYTES (2 * GBUF * 4)

__global__ __launch_bounds__(256, 2)
void gemm_pipe(const float* __restrict__ A, const float* __restrict__ W,
               const float* __restrict__ bias, const float* __restrict__ res,
               float* __restrict__ C, uint32_t* __restrict__ Ct,
               int N, int Kd, int mode) {
    extern __shared__ uint32_t sm[];

    int tid  = threadIdx.x;
    int lane = tid & 31, wid = tid >> 5;
    int g = lane >> 2, t = lane & 3;
    int m0 = blockIdx.y * GBM;
    int n0 = blockIdx.x * GBN;
    int wm = (wid & 1) * 64;
    int wn = (wid >> 1) * 32;

    int r0 = tid >> 3, kg = tid & 7;
    uint32_t smbase = smem_u32(sm);
    uint32_t adst[4], bdst[4];
    const float* asrc[4];
    const float* bsrc[4];
    uint32_t bok[4];
#pragma unroll
    for (int i = 0; i < 4; i++) {
        int r = r0 + i * 32;
        adst[i] = smbase + (uint32_t)(r * SPITCH + kg * 4) * 4;
        bdst[i] = adst[i] + GBM * SPITCH * 4;
        asrc[i] = A + (size_t)(m0 + r) * Kd + kg * 4;
        int n = n0 + r;
        bok[i] = (n < N) ? 16u : 0u;
        bsrc[i] = W + (size_t)((n < N) ? n : 0) * Kd + kg * 4;
    }

    float acc[4][4][4];
#pragma unroll
    for (int mt = 0; mt < 4; mt++)
#pragma unroll
        for (int nt = 0; nt < 4; nt++)
#pragma unroll
            for (int i = 0; i < 4; i++) acc[mt][nt][i] = 0.f;

    const int KT = (Kd + GBK - 1) / GBK;

    {
        int k = kg * 4;
        uint32_t kin = (k < Kd) ? 16u : 0u;
#pragma unroll
        for (int i = 0; i < 4; i++) {
            const float* sa = kin ? asrc[i] : A;
            asm volatile("cp.async.ca.shared.global [%0], [%1], 16, %2;"
                         :: "r"(adst[i]), "l"(sa), "r"(kin) : "memory");
            uint32_t bb = kin & bok[i];
            const float* sb = bb ? bsrc[i] : W;
            asm volatile("cp.async.ca.shared.global [%0], [%1], 16, %2;"
                         :: "r"(bdst[i]), "l"(sb), "r"(bb) : "memory");
        }
        CPCOMMIT();
    }

    for (int kt = 0; kt < KT; kt++) {
        int buf = kt & 1;
        if (kt + 1 < KT) {
            int k0 = (kt + 1) * GBK;
            int k = k0 + kg * 4;
            uint32_t kin = (k < Kd) ? 16u : 0u;
            uint32_t bo = (buf ^ 1) ? (uint32_t)GBUF * 4 : 0u;
#pragma unroll
            for (int i = 0; i < 4; i++) {
                const float* sa = kin ? (asrc[i] + k0) : A;
                asm volatile("cp.async.ca.shared.global [%0], [%1], 16, %2;"
                             :: "r"(adst[i] + bo), "l"(sa), "r"(kin) : "memory");
                uint32_t bb = kin & bok[i];
                const float* sb = bb ? (bsrc[i] + k0) : W;
                asm volatile("cp.async.ca.shared.global [%0], [%1], 16, %2;"
                             :: "r"(bdst[i] + bo), "l"(sb), "r"(bb) : "memory");
            }
            CPCOMMIT();
            asm volatile("cp.async.wait_group 1;" ::: "memory");
        } else {
            asm volatile("cp.async.wait_group 0;" ::: "memory");
        }
        __syncthreads();

        const uint32_t* Ab = sm + (buf ? GBUF : 0);
        const uint32_t* Bb = Ab + GBM * SPITCH;
#pragma unroll
        for (int ks = 0; ks < 4; ks++) {
            int kk = ks * 8;
            uint32_t af[4][4], bf[4][2];
#pragma unroll
            for (int mt = 0; mt < 4; mt++) {
                const uint32_t* Ar = Ab + (wm + mt * 16 + g) * SPITCH + kk;
                af[mt][0] = Ar[t];
                af[mt][1] = Ar[8 * SPITCH + t];
                af[mt][2] = Ar[t + 4];
                af[mt][3] = Ar[8 * SPITCH + t + 4];
            }
#pragma unroll
            for (int nt = 0; nt < 4; nt++) {
                const uint32_t* Br = Bb + (wn + nt * 8 + g) * SPITCH + kk;
                bf[nt][0] = Br[t];
                bf[nt][1] = Br[t + 4];
            }
#pragma unroll
            for (int mt = 0; mt < 4; mt++)
#pragma unroll
                for (int nt = 0; nt < 4; nt++)
                    MMA_TF32(acc[mt][nt], af[mt], bf[nt]);
        }
        __syncthreads();
    }

#pragma unroll
    for (int mt = 0; mt < 4; mt++) {
        int row0 = m0 + wm + mt * 16 + g;
#pragma unroll
        for (int nt = 0; nt < 4; nt++) {
            int col = n0 + wn + nt * 8 + 2 * t;
            if (col < N) {
                float2 bv = *(const float2*)(bias + col);
                float2 o0, o1;
                o0.x = acc[mt][nt][0] + bv.x;
                o0.y = acc[mt][nt][1] + bv.y;
                o1.x = acc[mt][nt][2] + bv.x;
                o1.y = acc[mt][nt][3] + bv.y;
                if (mode == 2) {
                    // head-padded rounded qkv: col -> (which, head, d)
                    int which = col / 500;
                    int rem   = col - which * 500;
                    int hh    = rem / 50;
                    int dd    = rem - hh * 50;
                    size_t p0 = (size_t)row0 * QKVP + which * 640 + hh * 64 + dd;
                    size_t p1 = (size_t)(row0 + 8) * QKVP + which * 640 + hh * 64 + dd;
                    uint32_t* Cq = (uint32_t*)C;
                    *(uint2*)(Cq + p0) = make_uint2(f2tf32(o0.x), f2tf32(o0.y));
                    *(uint2*)(Cq + p1) = make_uint2(f2tf32(o1.x), f2tf32(o1.y));
                } else {
                    size_t i0 = (size_t)row0 * N + col;
                    size_t i1 = (size_t)(row0 + 8) * N + col;
                    if (res) {
                        float2 r0v = *(const float2*)(res + i0);
                        float2 r1v = *(const float2*)(res + i1);
                        o0.x += r0v.x; o0.y += r0v.y;
                        o1.x += r1v.x; o1.y += r1v.y;
                    }
                    *(float2*)(C + i0) = o0;
                    *(float2*)(C + i1) = o1;
                    if (mode == 1) {
                        *(uint2*)(Ct + i0) = make_uint2(f2tf32(o0.x), f2tf32(o0.y));
                        *(uint2*)(Ct + i1) = make_uint2(f2tf32(o1.x), f2tf32(o1.y));
                    }
                }
            }
        }
    }
}

// =================== tf32 warp-mma flash attention ==========================
// qkv2 is tf32-pre-rounded, head-padded [BT][3*H*64]. Staging = pure copies.
#define AMQ 128
#define ANK 64
#define ADP 56
#define APQ 60
#define APV 68
#define ASM_BYTES ((AMQ*APQ + ANK*APQ + ADP*APV + AMQ*APV) * 4 + 64)

__global__ __launch_bounds__(256, 2)
void attn_mma(const float* __restrict__ qkv2,
              const unsigned char* __restrict__ mask,
              uint32_t* __restrict__ out) {
    extern __shared__ uint32_t dsm[];
    uint32_t* Qs = dsm;                    // [128][60]
    uint32_t* Ks = Qs + AMQ * APQ;         // [64][60]
    uint32_t* Vt = Ks + ANK * APQ;         // [56][68]
    uint32_t* Ps = Vt + ADP * APV;         // [128][68]
    unsigned char* msk = (unsigned char*)(Ps + AMQ * APV);

    int tid  = threadIdx.x;
    int lane = tid & 31, wid = tid >> 5;
    int g = lane >> 2, t = lane & 3;
    int bh = blockIdx.y;
    int b  = bh / H, h = bh % H;
    int q0 = blockIdx.x * AMQ;
    const float scale = 0.14142135623730951f;

    // zero pad columns/rows once (never rewritten)
    for (int i = tid; i < AMQ * 6; i += 256) Qs[(i / 6) * APQ + 50 + (i % 6)] = 0;
    for (int i = tid; i < ANK * 6; i += 256) Ks[(i / 6) * APQ + 50 + (i % 6)] = 0;
    for (int i = tid; i < 6 * APV; i += 256) Vt[(50 + i / APV) * APV + (i % APV)] = 0;

    // stage Q via cp.async bulk copy (12x16B + 8B per row)
    {
        int r = tid >> 1, e = tid & 1;
        const float* src = qkv2 + (size_t)(b * T + q0 + r) * QKVP + h * 64;
        uint32_t dst = smem_u32(Qs + r * APQ);
#pragma unroll
        for (int c = e; c < 12; c += 2) CP16(dst + 16 * c, src + 4 * c);
        if (e == 0) CP8(dst + 192, src + 48);
        CPCOMMIT();
    }

    int wq = wid * 16;
    const uint32_t* QA = Qs + (wq + g) * APQ;
    const uint32_t* QB = Qs + (wq + g + 8) * APQ;
    uint32_t* PsA = Ps + (wq + g) * APV;
    uint32_t* PsB = Ps + (wq + g + 8) * APV;

    float m0 = -1e30f, m1 = -1e30f, l0 = 0.f, l1 = 0.f;
    float oacc[7][4];
#pragma unroll
    for (int nt = 0; nt < 7; nt++)
#pragma unroll
        for (int i = 0; i < 4; i++) oacc[nt][i] = 0.f;

    for (int kt = 0; kt < T / ANK; kt++) {
        int k0 = kt * ANK;
        __syncthreads();   // prior tile fully consumed

        // K via cp.async (overlaps with V manual transpose below)
        {
            int j = tid >> 2, q = tid & 3;
            const float* src = qkv2 + (size_t)(b * T + k0 + j) * QKVP + 640 + h * 64;
            uint32_t dst = smem_u32(Ks + j * APQ);
            CP16(dst + 16 * q,       src + 4 * q);
            CP16(dst + 16 * (q + 4), src + 4 * (q + 4));
            CP16(dst + 16 * (q + 8), src + 4 * (q + 8));
            if (q == 3) CP8(dst + 192, src + 48);
            CPCOMMIT();
        }
        // V manual transpose (float2 loads, conflict-free scattered STS)
        {
            int j = tid >> 2, q = tid & 3;
            const float* src = qkv2 + (size_t)(b * T + k0 + j) * QKVP + 1280 + h * 64;
#pragma unroll
            for (int p = q; p < 25; p += 4) {
                float2 v = *(const float2*)(src + 2 * p);
                Vt[(2 * p) * APV + j]     = __float_as_uint(v.x);
                Vt[(2 * p + 1) * APV + j] = __float_as_uint(v.y);
            }
        }
        if (tid < ANK) msk[tid] = mask[b * T + k0 + tid];
        CPWAIT0();
        __syncthreads();

        // ---- S = Q K^T (scale applied after)
        float sacc[8][4];
#pragma unroll
        for (int nt = 0; nt < 8; nt++)
#pragma unroll
            for (int i = 0; i < 4; i++) sacc[nt][i] = 0.f;
#pragma unroll
        for (int ks = 0; ks < 7; ks++) {
            int kk = ks * 8;
            uint32_t af[4] = {QA[kk + t], QB[kk + t], QA[kk + t + 4], QB[kk + t + 4]};
#pragma unroll
            for (int nt = 0; nt < 8; nt++) {
                const uint32_t* Kr = Ks + (nt * 8 + g) * APQ + kk;
                uint32_t bf[2] = {Kr[t], Kr[t + 4]};
                MMA_TF32(sacc[nt], af, bf);
            }
        }

        // ---- scale + mask + online softmax
        float mx0 = -1e30f, mx1 = -1e30f;
#pragma unroll
        for (int nt = 0; nt < 8; nt++) {
            sacc[nt][0] *= scale; sacc[nt][1] *= scale;
            sacc[nt][2] *= scale; sacc[nt][3] *= scale;
            int c = nt * 8 + 2 * t;
            if (msk[c])     { sacc[nt][0] = -1e30f; sacc[nt][2] = -1e30f; }
            if (msk[c + 1]) { sacc[nt][1] = -1e30f; sacc[nt][3] = -1e30f; }
            mx0 = fmaxf(mx0, fmaxf(sacc[nt][0], sacc[nt][1]));
            mx1 = fmaxf(mx1, fmaxf(sacc[nt][2], sacc[nt][3]));
        }
        mx0 = fmaxf(mx0, __shfl_xor_sync(0xffffffffu, mx0, 1));
        mx0 = fmaxf(mx0, __shfl_xor_sync(0xffffffffu, mx0, 2));
        mx1 = fmaxf(mx1, __shfl_xor_sync(0xffffffffu, mx1, 1));
        mx1 = fmaxf(mx1, __shfl_xor_sync(0xffffffffu, mx1, 2));
        float mn0 = fmaxf(m0, mx0), mn1 = fmaxf(m1, mx1);
        float c0 = __expf(m0 - mn0), c1 = __expf(m1 - mn1);
        float s0 = 0.f, s1 = 0.f;
#pragma unroll
        for (int nt = 0; nt < 8; nt++) {
            float p00 = __expf(sacc[nt][0] - mn0);
            float p01 = __expf(sacc[nt][1] - mn0);
            float p10 = __expf(sacc[nt][2] - mn1);
            float p11 = __expf(sacc[nt][3] - mn1);
            s0 += p00 + p01;
            s1 += p10 + p11;
            int c = nt * 8 + 2 * t;
            *(uint2*)(PsA + c) = make_uint2(f2tf32(p00), f2tf32(p01));
            *(uint2*)(PsB + c) = make_uint2(f2tf32(p10), f2tf32(p11));
        }
        s0 += __shfl_xor_sync(0xffffffffu, s0, 1);
        s0 += __shfl_xor_sync(0xffffffffu, s0, 2);
        s1 += __shfl_xor_sync(0xffffffffu, s1, 1);
        s1 += __shfl_xor_sync(0xffffffffu, s1, 2);
        l0 = l0 * c0 + s0; m0 = mn0;
        l1 = l1 * c1 + s1; m1 = mn1;
#pragma unroll
        for (int nt = 0; nt < 7; nt++) {
            oacc[nt][0] *= c0; oacc[nt][1] *= c0;
            oacc[nt][2] *= c1; oacc[nt][3] *= c1;
        }
        __syncwarp();

        // ---- O += P V
#pragma unroll
        for (int ks = 0; ks < 8; ks++) {
            int kk = ks * 8;
            uint32_t af[4] = {PsA[kk + t], PsB[kk + t], PsA[kk + t + 4], PsB[kk + t + 4]};
#pragma unroll
            for (int nt = 0; nt < 7; nt++) {
                const uint32_t* Vr = Vt + (nt * 8 + g) * APV + kk;
                uint32_t bf[2] = {Vr[t], Vr[t + 4]};
                MMA_TF32(oacc[nt], af, bf);
            }
        }
    }

    // epilogue: O / l, tf32-rounded (consumer is out_proj GEMM A)
    float inv0 = 1.f / l0, inv1 = 1.f / l1;
    int r0 = q0 + wq + g;
    uint32_t* o0 = out + (size_t)(b * T + r0) * D + h * HD;
    uint32_t* o1 = o0 + (size_t)8 * D;
#pragma unroll
    for (int nt = 0; nt < 7; nt++) {
        int c = nt * 8 + 2 * t;
        if (c < HD) {
            *(uint2*)(o0 + c) = make_uint2(f2tf32(oacc[nt][0] * inv0),
                                           f2tf32(oacc[nt][1] * inv0));
            *(uint2*)(o1 + c) = make_uint2(f2tf32(oacc[nt][2] * inv1),
                                           f2tf32(oacc[nt][3] * inv1));
        }
    }
}

// ---------------- launch ----------------------------------------------------
extern "C" void kernel_launch(void* const* d_in, const int* in_sizes, int n_in,
                              void* d_out, int out_size) {
    const int* ori            = (const int*)d_in[0];
    const float* x            = (const float*)d_in[1];
    const unsigned char* xm   = (const unsigned char*)d_in[2];
    const float *dwp[4], *dbp[4], *pwp[4], *pbp[4];
    for (int i = 0; i < 4; i++) {
        dwp[i] = (const float*)d_in[3 + 4 * i];
        dbp[i] = (const float*)d_in[4 + 4 * i];
        pwp[i] = (const float*)d_in[5 + 4 * i];
        pbp[i] = (const float*)d_in[6 + 4 * i];
    }
    const float* in_w  = (const float*)d_in[19];
    const float* in_b  = (const float*)d_in[20];
    const float* out_w = (const float*)d_in[21];
    const float* out_b = (const float*)d_in[22];
    const float* ffc_w = (const float*)d_in[23];
    const float* ffc_b = (const float*)d_in[24];
    float* outp = (float*)d_out;

    float *b0, *b1, *b2, *bt, *b1t, *b2t, *qkvp, *wt;
    cudaGetSymbolAddress((void**)&b0,   g_b0);
    cudaGetSymbolAddress((void**)&b1,   g_b1);
    cudaGetSymbolAddress((void**)&b2,   g_b2);
    cudaGetSymbolAddress((void**)&bt,   g_bt);
    cudaGetSymbolAddress((void**)&b1t,  g_b1t);
    cudaGetSymbolAddress((void**)&b2t,  g_b2t);
    cudaGetSymbolAddress((void**)&qkvp, g_qkv);
    cudaGetSymbolAddress((void**)&wt,   g_wt);

    cudaFuncSetAttribute(attn_mma, cudaFuncAttributeMaxDynamicSharedMemorySize, ASM_BYTES);
    cudaFuncSetAttribute(gemm_pipe, cudaFuncAttributeMaxDynamicSharedMemorySize, GSM_BYTES);

    const int DD = D * D;
    float* wtp[4];
    for (int i = 0; i < 4; i++) wtp[i] = wt + i * DD;
    float* wt_in  = wt + 4 * DD;
    float* wt_out = wt_in + D3 * D;
    float* wt_ffc = wt_out + DD;

    int ncvt = 6 * DD + D3 * D;
    cvt_all<<<(ncvt + 255) / 256, 256>>>(pwp[0], pwp[1], pwp[2], pwp[3],
                                         in_w, out_w, ffc_w, (uint32_t*)wt);

    int eblocks  = (BTD + 255) / 256;
    int e4blocks = (BTD / 4 + 255) / 256;
    dim3 gg5((D + GBN - 1) / GBN, BT / GBM);    // (4, 128)
    dim3 ggq((D3 + GBN - 1) / GBN, BT / GBM);   // (12, 128)
    dim3 gga(T / AMQ, B * H);                   // (4, 320)

    posemb_kernel<<<eblocks, 256>>>(ori, x, b0);
    dwconv4_kernel<<<e4blocks, 256>>>(b0, dwp[0], dbp[0], (uint32_t*)bt);
    gemm_pipe<<<gg5, 256, GSM_BYTES>>>(bt, wtp[0], pbp[0], b0, b1, nullptr, D, D, 0);
    dwconv4_kernel<<<e4blocks, 256>>>(b1, dwp[1], dbp[1], (uint32_t*)bt);
    gemm_pipe<<<gg5, 256, GSM_BYTES>>>(bt, wtp[1], pbp[1], b1, b2, nullptr, D, D, 0);
    dwconv4_kernel<<<e4blocks, 256>>>(b2, dwp[2], dbp[2], (uint32_t*)bt);
    gemm_pipe<<<gg5, 256, GSM_BYTES>>>(bt, wtp[2], pbp[2], b2, b0, nullptr, D, D, 0);
    dwconv4_kernel<<<e4blocks, 256>>>(b0, dwp[3], dbp[3], (uint32_t*)bt);
    gemm_pipe<<<gg5, 256, GSM_BYTES>>>(bt, wtp[3], pbp[3], b0, b1, (uint32_t*)b1t, D, D, 1);
    gemm_pipe<<<ggq, 256, GSM_BYTES>>>(b1t, wt_in, in_b, nullptr, qkvp, nullptr, D3, D, 2);
    attn_mma<<<gga, 256, ASM_BYTES>>>(qkvp, xm, (uint32_t*)bt);
    gemm_pipe<<<gg5, 256, GSM_BYTES>>>(bt, wt_out, out_b, b1, b2, (uint32_t*)b2t, D, D, 1);
    gemm_pipe<<<gg5, 256, GSM_BYTES>>>(b2t, wt_ffc, ffc_b, b2, outp, nullptr, D, D, 0);
}